// round 13
// baseline (speedup 1.0000x reference)
#include <cuda_runtime.h>
#include <cuda_fp16.h>
#include <cstdint>

#define NN 65536
#define NE 1048576
#define DD 128

// ---------------- device scratch (static, allocation-free) ----------------
__device__ float g_h[NN * DD];      // residual stream
__device__ float g_xl[NN * DD];     // x @ Wl + bl
__device__ float g_xr[NN * DD];     // x @ Wr + br
__device__ int2  g_se[NE];          // CSR (by dst): packed {src, ea_bits}
__device__ int   g_cnt[NN];         // zero at load; re-zeroed by k_apply each call
__device__ int   g_off[NN + 1];
__device__ int   g_cur[NN];
__device__ int   g_bsum[256];
__device__ float g_part[1024];
__device__ float g_eamean;

__device__ __forceinline__ uint32_t pkh2(float lo, float hi) {
    __half2 h = __floats2half2_rn(lo, hi);
    return *(uint32_t*)&h;
}

// ---------------- setup 1: histogram of dst + partial sums of edge_attr ----------------
__global__ void k_prep(const int* __restrict__ dst, const float* __restrict__ ea) {
    __shared__ float sm[256];
    int base = blockIdx.x * 1024;
    float s = 0.f;
#pragma unroll
    for (int i = 0; i < 4; i++) {
        int e = base + threadIdx.x + i * 256;
        atomicAdd(&g_cnt[dst[e]], 1);
        s += ea[e];
    }
    sm[threadIdx.x] = s;
    __syncthreads();
    for (int o = 128; o > 0; o >>= 1) {
        if (threadIdx.x < o) sm[threadIdx.x] += sm[threadIdx.x + o];
        __syncthreads();
    }
    if (threadIdx.x == 0) g_part[blockIdx.x] = sm[0];
}

// ---------------- setup 2: per-256-chunk sums of g_cnt ----------------
__global__ void k_blocksum() {
    __shared__ int sm[256];
    int i = blockIdx.x * 256 + threadIdx.x;
    sm[threadIdx.x] = g_cnt[i];
    __syncthreads();
    for (int o = 128; o > 0; o >>= 1) {
        if (threadIdx.x < o) sm[threadIdx.x] += sm[threadIdx.x + o];
        __syncthreads();
    }
    if (threadIdx.x == 0) g_bsum[blockIdx.x] = sm[0];
}

// ---------------- setup 3: per-block scan + ea mean; re-zero g_cnt ----------
__global__ void k_apply() {
    __shared__ int bs[256];
    __shared__ int cs[256];
    __shared__ float fs[256];
    int tid = threadIdx.x;

    if (blockIdx.x == 0) {
        float s = g_part[tid] + g_part[tid + 256] + g_part[tid + 512] + g_part[tid + 768];
        fs[tid] = s;
    }

    int bv = g_bsum[tid];
    bs[tid] = bv;
    __syncthreads();
    for (int o = 1; o < 256; o <<= 1) {
        int t = (tid >= o) ? bs[tid - o] : 0;
        __syncthreads();
        bs[tid] += t;
        __syncthreads();
    }
    int boff = bs[blockIdx.x] - g_bsum[blockIdx.x];
    if (blockIdx.x == 255 && tid == 255) g_off[NN] = bs[255];

    int i = blockIdx.x * 256 + tid;
    int c = g_cnt[i];
    g_cnt[i] = 0;                 // ready for the next graph replay
    cs[tid] = c;
    __syncthreads();
    for (int o = 1; o < 256; o <<= 1) {
        int t = (tid >= o) ? cs[tid - o] : 0;
        __syncthreads();
        cs[tid] += t;
        __syncthreads();
    }
    int off = boff + cs[tid] - c;
    g_off[i] = off;
    g_cur[i] = off;

    if (blockIdx.x == 0) {
        for (int o = 128; o > 0; o >>= 1) {
            if (tid < o) fs[tid] += fs[tid + o];
            __syncthreads();
        }
        if (tid == 0) g_eamean = fs[0] * (1.f / (float)NE);
    }
}

// ---------------- GEMM (fp16 mma m16n8k16) + fused CSR scatter --------------
// Blocks [0,512): GEMM tiles. Blocks [512, 512+4096): scatter (layer 0 only).
#define SMPA 132
#define SMPB 136

__global__ __launch_bounds__(256, 2)
void k_gemm(const float* __restrict__ A,
            const float* __restrict__ Wl, const float* __restrict__ bl,
            const float* __restrict__ Wr, const float* __restrict__ br,
            const int* __restrict__ esrc, const int* __restrict__ edst,
            const float* __restrict__ eattr) {
    if (blockIdx.x >= 512) {  // fused scatter blocks (overlap the GEMM tail)
        int e = (blockIdx.x - 512) * 256 + threadIdx.x;
        int d = edst[e];
        int idx = atomicAdd(&g_cur[d], 1);
        g_se[idx] = make_int2(esrc[e], __float_as_int(eattr[e]));
        return;
    }

    extern __shared__ uint32_t smw[];
    uint32_t* As = smw;              // 64 frag-rows (Rg*8+kb) x SMPA words
    uint32_t* Bs = smw + 64 * SMPA;  // 32 half2-k-rows x SMPB (one K-half)

    int tid = threadIdx.x;
    int rowBase = blockIdx.x * 128;
    int lane = tid & 31, warp = tid >> 5;
    int wr = warp & 1, wc = warp >> 1;       // 2 row-groups x 4 col-groups
    int r0 = wr * 64, c0 = wc * 32;
    int g = lane >> 2, t = lane & 3;

    // load A tile once, fragment-packed fp16
#pragma unroll
    for (int i = 0; i < 16; i++) {
        int lin = tid + 256 * i;
        int r = lin >> 5;                    // 0..127
        int c4 = (lin & 31) << 2;            // 0,4,..,124
        float4 hv = *(const float4*)(A + (size_t)(rowBase + r) * DD + c4);
        int Rg = r >> 4, gg = r & 7, p = (r >> 3) & 1;
        int kb = c4 >> 4;
        int hk = (c4 & 15) >> 1;             // 0,2,4,6
        int t0 = hk & 3;                     // 0 or 2
        int q2 = hk >> 2;                    // 0 or 1
        uint32_t* pa = &As[(Rg * 8 + kb) * SMPA + gg * 16 + p + 2 * q2];
        pa[t0 * 4]       = pkh2(hv.x, hv.y);
        pa[(t0 + 1) * 4] = pkh2(hv.z, hv.w);
    }

    for (int side = 0; side < 2; side++) {
        const float* W    = side ? Wr : Wl;
        const float* bias = side ? br : bl;
        float* out        = side ? g_xr : g_xl;

        float acc[4][4][4];
#pragma unroll
        for (int mi = 0; mi < 4; mi++)
#pragma unroll
            for (int ni = 0; ni < 4; ni++)
#pragma unroll
                for (int q = 0; q < 4; q++) acc[mi][ni][q] = 0.f;

        for (int kh = 0; kh < 2; kh++) {
            __syncthreads();  // previous Bs fully consumed
#pragma unroll
            for (int i = 0; i < 4; i++) {
                int lin = tid + 256 * i;          // 1024 total
                int r2 = lin >> 5;                // 0..31 (k-pair)
                int c4 = (lin & 31) << 2;
                const float* w0 = W + (size_t)(kh * 64 + 2 * r2) * DD + c4;
                float4 wa = *(const float4*)w0;
                float4 wb = *(const float4*)(w0 + DD);
                uint32_t* pb = &Bs[r2 * SMPB + c4];
                pb[0] = pkh2(wa.x, wb.x);
                pb[1] = pkh2(wa.y, wb.y);
                pb[2] = pkh2(wa.z, wb.z);
                pb[3] = pkh2(wa.w, wb.w);
            }
            __syncthreads();

#pragma unroll
            for (int ks = 0; ks < 4; ks++) {      // 4 k16-steps per half
                int kb = kh * 4 + ks;
                uint4 a[4];
#pragma unroll
                for (int mi = 0; mi < 4; mi++) {
                    int Rg = wr * 4 + mi;
                    a[mi] = *(const uint4*)&As[(Rg * 8 + kb) * SMPA + lane * 4];
                }
#pragma unroll
                for (int ni = 0; ni < 4; ni++) {
                    int nb = c0 + ni * 8 + g;
                    uint32_t b0 = Bs[(ks * 8 + t) * SMPB + nb];
                    uint32_t b1 = Bs[(ks * 8 + t + 4) * SMPB + nb];
#pragma unroll
                    for (int mi = 0; mi < 4; mi++) {
                        asm volatile(
                            "mma.sync.aligned.m16n8k16.row.col.f32.f16.f16.f32 "
                            "{%0,%1,%2,%3},{%4,%5,%6,%7},{%8,%9},{%0,%1,%2,%3};"
                            : "+f"(acc[mi][ni][0]), "+f"(acc[mi][ni][1]),
                              "+f"(acc[mi][ni][2]), "+f"(acc[mi][ni][3])
                            : "r"(a[mi].x), "r"(a[mi].y), "r"(a[mi].z), "r"(a[mi].w),
                              "r"(b0), "r"(b1));
                    }
                }
            }
        }

#pragma unroll
        for (int mi = 0; mi < 4; mi++) {
#pragma unroll
            for (int ni = 0; ni < 4; ni++) {
                int cc = c0 + ni * 8 + 2 * t;
                float b0v = bias[cc], b1v = bias[cc + 1];
                int rr = rowBase + r0 + mi * 16 + g;
                *(float2*)(out + (size_t)rr * DD + cc) =
                    make_float2(acc[mi][ni][0] + b0v, acc[mi][ni][1] + b1v);
                *(float2*)(out + (size_t)(rr + 8) * DD + cc) =
                    make_float2(acc[mi][ni][2] + b0v, acc[mi][ni][3] + b1v);
            }
        }
    }
}

// ---------------- fused edge kernel: scalar fp32, 2-way chains, hi-occ ------
// alpha = e^a / sum e^a (no max-shift: logits O(1), overflow-impossible).
template <int H>
__device__ __forceinline__ float edge_w(float4 x4, float4 xr4, float4 at4,
                                        float4 we4, float eav) {
    float m0 = x4.x + xr4.x + eav * we4.x;
    float m1 = x4.y + xr4.y + eav * we4.y;
    float m2 = x4.z + xr4.z + eav * we4.z;
    float m3 = x4.w + xr4.w + eav * we4.w;
    m0 = (m0 >= 0.f) ? m0 : 0.2f * m0;
    m1 = (m1 >= 0.f) ? m1 : 0.2f * m1;
    m2 = (m2 >= 0.f) ? m2 : 0.2f * m2;
    m3 = (m3 >= 0.f) ? m3 : 0.2f * m3;
    float p = m0 * at4.x + m1 * at4.y + m2 * at4.z + m3 * at4.w;
    p += __shfl_xor_sync(0xffffffffu, p, 1);
    p += __shfl_xor_sync(0xffffffffu, p, 2);
    p += __shfl_xor_sync(0xffffffffu, p, 4);
    if (H == 1) {
        p += __shfl_xor_sync(0xffffffffu, p, 8);
        p += __shfl_xor_sync(0xffffffffu, p, 16);
    }
    return __expf(p);
}

template <int H, bool LAST>
__global__ __launch_bounds__(256, 5)
void k_edge(const float* __restrict__ hin,
            const float* __restrict__ att, const float* __restrict__ Wev,
            const float* __restrict__ bp, const float* __restrict__ lng,
            const float* __restrict__ lnb, float* __restrict__ dout) {
    int n = blockIdx.x * 8 + (threadIdx.x >> 5);
    int l = threadIdx.x & 31;
    int col = l * 4;

    float4 xr4 = *(const float4*)(g_xr + (size_t)n * DD + col);
    float4 at4 = *(const float4*)(att + col);
    float4 we4 = *(const float4*)(Wev + col);
    int e0 = g_off[n], e1 = g_off[n + 1];

    // self-loop first (src=n, ea=mean)
    float4 xs = *(const float4*)(g_xl + (size_t)n * DD + col);
    float ws = edge_w<H>(xs, xr4, at4, we4, g_eamean);
    float ss = ws;
    float a0 = ws * xs.x, a1 = ws * xs.y, a2 = ws * xs.z, a3 = ws * xs.w;
    float ss2 = 0.f, b0 = 0.f, b1 = 0.f, b2 = 0.f, b3 = 0.f;

    int e = e0;
    int2 q0, q1;
    if (e + 2 <= e1) { q0 = g_se[e]; q1 = g_se[e + 1]; }
    for (; e + 2 <= e1; ) {  // two independent chains + q-prefetch
        float4 xa = *(const float4*)(g_xl + (size_t)q0.x * DD + col);
        float4 xb = *(const float4*)(g_xl + (size_t)q1.x * DD + col);
        float ea0 = __int_as_float(q0.y), ea1 = __int_as_float(q1.y);
        e += 2;
        if (e + 2 <= e1) { q0 = g_se[e]; q1 = g_se[e + 1]; }  // prefetch next pair
        float wa = edge_w<H>(xa, xr4, at4, we4, ea0);
        float wb = edge_w<H>(xb, xr4, at4, we4, ea1);
        ss += wa;  a0 += wa * xa.x; a1 += wa * xa.y; a2 += wa * xa.z; a3 += wa * xa.w;
        ss2 += wb; b0 += wb * xb.x; b1 += wb * xb.y; b2 += wb * xb.z; b3 += wb * xb.w;
    }
    if (e < e1) {
        int2 qz = g_se[e];
        float4 xa = *(const float4*)(g_xl + (size_t)qz.x * DD + col);
        float wa = edge_w<H>(xa, xr4, at4, we4, __int_as_float(qz.y));
        ss += wa; a0 += wa * xa.x; a1 += wa * xa.y; a2 += wa * xa.z; a3 += wa * xa.w;
    }
    ss += ss2; a0 += b0; a1 += b1; a2 += b2; a3 += b3;

    float4 bp4 = *(const float4*)(bp + col);
    float inv = 1.f / (ss + 1e-16f);
    float o0 = a0 * inv + bp4.x;
    float o1 = a1 * inv + bp4.y;
    float o2 = a2 * inv + bp4.z;
    float o3 = a3 * inv + bp4.w;

    // LayerNorm over 128 (warp-wide reduce)
    float s1 = o0 + o1 + o2 + o3;
    s1 += __shfl_xor_sync(0xffffffffu, s1, 1);
    s1 += __shfl_xor_sync(0xffffffffu, s1, 2);
    s1 += __shfl_xor_sync(0xffffffffu, s1, 4);
    s1 += __shfl_xor_sync(0xffffffffu, s1, 8);
    s1 += __shfl_xor_sync(0xffffffffu, s1, 16);
    float mu = s1 * (1.f / 128.f);
    float d0 = o0 - mu, d1 = o1 - mu, d2 = o2 - mu, d3 = o3 - mu;
    float q = d0 * d0 + d1 * d1 + d2 * d2 + d3 * d3;
    q += __shfl_xor_sync(0xffffffffu, q, 1);
    q += __shfl_xor_sync(0xffffffffu, q, 2);
    q += __shfl_xor_sync(0xffffffffu, q, 4);
    q += __shfl_xor_sync(0xffffffffu, q, 8);
    q += __shfl_xor_sync(0xffffffffu, q, 16);
    float rs = rsqrtf(q * (1.f / 128.f) + 1e-5f);
    float4 g4 = *(const float4*)(lng + col);
    float4 b4 = *(const float4*)(lnb + col);
    float y0 = d0 * rs * g4.x + b4.x;
    float y1 = d1 * rs * g4.y + b4.y;
    float y2 = d2 * rs * g4.z + b4.z;
    float y3 = d3 * rs * g4.w + b4.w;

    if (!LAST) {  // exact GELU
        const float k = 0.70710678118654752f;
        y0 = 0.5f * y0 * (1.f + erff(y0 * k));
        y1 = 0.5f * y1 * (1.f + erff(y1 * k));
        y2 = 0.5f * y2 * (1.f + erff(y2 * k));
        y3 = 0.5f * y3 * (1.f + erff(y3 * k));
    }

    float4 h4 = *(const float4*)(hin + (size_t)n * DD + col);
    h4.x += y0; h4.y += y1; h4.z += y2; h4.w += y3;

    if (!LAST) {
        *(float4*)(g_h + (size_t)n * DD + col) = h4;
    } else {  // to_dense_batch(128, 512, 128)[:, :-1, :]
        int gi = n >> 9, ii = n & 511;
        if (ii != 511)
            *(float4*)(dout + ((size_t)(gi * 511 + ii)) * DD + col) = h4;
    }
}

// ---------------- launch ----------------
extern "C" void kernel_launch(void* const* d_in, const int* in_sizes, int n_in,
                              void* d_out, int out_size) {
    const float* x     = (const float*)d_in[0];
    const int*   esrc  = (const int*)d_in[1];
    const int*   edst  = (const int*)d_in[2];
    const float* eattr = (const float*)d_in[3];
    const float* Wl    = (const float*)d_in[4];
    const float* bl    = (const float*)d_in[5];
    const float* Wr    = (const float*)d_in[6];
    const float* br    = (const float*)d_in[7];
    const float* We    = (const float*)d_in[8];
    const float* att   = (const float*)d_in[9];
    const float* bp    = (const float*)d_in[10];
    const float* lng   = (const float*)d_in[11];
    const float* lnb   = (const float*)d_in[12];
    float* out = (float*)d_out;

    void* p_h = 0; cudaGetSymbolAddress(&p_h, g_h);

    const int GSM = 64 * SMPA * 4 + 32 * SMPB * 4;  // 51200 B -> 2 CTAs/SM
    cudaFuncSetAttribute(k_gemm, cudaFuncAttributeMaxDynamicSharedMemorySize, GSM);

    k_prep<<<1024, 256>>>(edst, eattr);
    k_blocksum<<<256, 256>>>();
    k_apply<<<256, 256>>>();
    // layer-0 GEMM + fused scatter (scatter blocks fill the GEMM tail)
    k_gemm<<<512 + NE / 256, 256, GSM>>>(x, Wl, bl, Wr, br, esrc, edst, eattr);

    const float* hsrc = (const float*)p_h;
    k_edge<4, false><<<NN / 8, 256>>>(x, att, We, bp, lng, lnb, out);
    for (int i = 1; i < 3; i++) {
        k_gemm<<<512, 256, GSM>>>(
            hsrc, Wl + i * 16384, bl + i * 128, Wr + i * 16384, br + i * 128,
            esrc, edst, eattr);
        if (i < 2)
            k_edge<4, false><<<NN / 8, 256>>>(hsrc, att + i * 128, We + i * 128, bp + i * 128,
                                              lng + i * 128, lnb + i * 128, out);
        else
            k_edge<1, true><<<NN / 8, 256>>>(hsrc, att + i * 128, We + i * 128, bp + i * 128,
                                             lng + i * 128, lnb + i * 128, out);
    }
}

// round 15
// speedup vs baseline: 1.0435x; 1.0435x over previous
#include <cuda_runtime.h>
#include <cuda_fp16.h>
#include <cstdint>

#define NN 65536
#define NE 1048576
#define DD 128

// ---------------- device scratch (static, allocation-free) ----------------
__device__ float g_h[NN * DD];      // residual stream
__device__ float g_xl[NN * DD];     // x @ Wl + bl
__device__ float g_xr[NN * DD];     // x @ Wr + br
__device__ int2  g_se[NE];          // CSR (by dst): packed {src, ea_bits}
__device__ int   g_cnt[NN];         // zero at load; re-zeroed by k_apply each call
__device__ int   g_off[NN + 1];
__device__ int   g_cur[NN];
__device__ int   g_bsum[256];
__device__ float g_part[1024];
__device__ float g_eamean;

__device__ __forceinline__ uint32_t pkh2(float lo, float hi) {
    __half2 h = __floats2half2_rn(lo, hi);
    return *(uint32_t*)&h;
}

// ---------------- setup 1: histogram of dst + partial sums of edge_attr ----------------
__global__ void k_prep(const int* __restrict__ dst, const float* __restrict__ ea) {
    __shared__ float sm[256];
    int base = blockIdx.x * 1024;
    float s = 0.f;
#pragma unroll
    for (int i = 0; i < 4; i++) {
        int e = base + threadIdx.x + i * 256;
        atomicAdd(&g_cnt[dst[e]], 1);
        s += ea[e];
    }
    sm[threadIdx.x] = s;
    __syncthreads();
    for (int o = 128; o > 0; o >>= 1) {
        if (threadIdx.x < o) sm[threadIdx.x] += sm[threadIdx.x + o];
        __syncthreads();
    }
    if (threadIdx.x == 0) g_part[blockIdx.x] = sm[0];
}

// ---------------- setup 2: per-256-chunk sums of g_cnt ----------------
__global__ void k_blocksum() {
    __shared__ int sm[256];
    int i = blockIdx.x * 256 + threadIdx.x;
    sm[threadIdx.x] = g_cnt[i];
    __syncthreads();
    for (int o = 128; o > 0; o >>= 1) {
        if (threadIdx.x < o) sm[threadIdx.x] += sm[threadIdx.x + o];
        __syncthreads();
    }
    if (threadIdx.x == 0) g_bsum[blockIdx.x] = sm[0];
}

// ---------------- setup 3: per-block scan + ea mean; re-zero g_cnt ----------
__global__ void k_apply() {
    __shared__ int bs[256];
    __shared__ int cs[256];
    __shared__ float fs[256];
    int tid = threadIdx.x;

    if (blockIdx.x == 0) {
        float s = g_part[tid] + g_part[tid + 256] + g_part[tid + 512] + g_part[tid + 768];
        fs[tid] = s;
    }

    int bv = g_bsum[tid];
    bs[tid] = bv;
    __syncthreads();
    for (int o = 1; o < 256; o <<= 1) {
        int t = (tid >= o) ? bs[tid - o] : 0;
        __syncthreads();
        bs[tid] += t;
        __syncthreads();
    }
    int boff = bs[blockIdx.x] - g_bsum[blockIdx.x];
    if (blockIdx.x == 255 && tid == 255) g_off[NN] = bs[255];

    int i = blockIdx.x * 256 + tid;
    int c = g_cnt[i];
    g_cnt[i] = 0;                 // ready for the next graph replay
    cs[tid] = c;
    __syncthreads();
    for (int o = 1; o < 256; o <<= 1) {
        int t = (tid >= o) ? cs[tid - o] : 0;
        __syncthreads();
        cs[tid] += t;
        __syncthreads();
    }
    int off = boff + cs[tid] - c;
    g_off[i] = off;
    g_cur[i] = off;

    if (blockIdx.x == 0) {
        for (int o = 128; o > 0; o >>= 1) {
            if (tid < o) fs[tid] += fs[tid + o];
            __syncthreads();
        }
        if (tid == 0) g_eamean = fs[0] * (1.f / (float)NE);
    }
}

// ---------------- GEMM (fp16 mma m16n8k16) + fused CSR scatter --------------
// Blocks [0,512): GEMM tiles. Blocks [512, 512+4096): scatter (layer 0 only).
#define SMPA 132
#define SMPB 136

__global__ __launch_bounds__(256, 2)
void k_gemm(const float* __restrict__ A,
            const float* __restrict__ Wl, const float* __restrict__ bl,
            const float* __restrict__ Wr, const float* __restrict__ br,
            const int* __restrict__ esrc, const int* __restrict__ edst,
            const float* __restrict__ eattr) {
    if (blockIdx.x >= 512) {  // fused scatter blocks (overlap the GEMM tail)
        int e = (blockIdx.x - 512) * 256 + threadIdx.x;
        int d = edst[e];
        int idx = atomicAdd(&g_cur[d], 1);
        g_se[idx] = make_int2(esrc[e], __float_as_int(eattr[e]));
        return;
    }

    extern __shared__ uint32_t smw[];
    uint32_t* As = smw;              // 64 frag-rows (Rg*8+kb) x SMPA words
    uint32_t* Bs = smw + 64 * SMPA;  // 32 half2-k-rows x SMPB (one K-half)

    int tid = threadIdx.x;
    int rowBase = blockIdx.x * 128;
    int lane = tid & 31, warp = tid >> 5;
    int wr = warp & 1, wc = warp >> 1;       // 2 row-groups x 4 col-groups
    int r0 = wr * 64, c0 = wc * 32;
    int g = lane >> 2, t = lane & 3;

    // load A tile once, fragment-packed fp16
#pragma unroll
    for (int i = 0; i < 16; i++) {
        int lin = tid + 256 * i;
        int r = lin >> 5;                    // 0..127
        int c4 = (lin & 31) << 2;            // 0,4,..,124
        float4 hv = *(const float4*)(A + (size_t)(rowBase + r) * DD + c4);
        int Rg = r >> 4, gg = r & 7, p = (r >> 3) & 1;
        int kb = c4 >> 4;
        int hk = (c4 & 15) >> 1;             // 0,2,4,6
        int t0 = hk & 3;                     // 0 or 2
        int q2 = hk >> 2;                    // 0 or 1
        uint32_t* pa = &As[(Rg * 8 + kb) * SMPA + gg * 16 + p + 2 * q2];
        pa[t0 * 4]       = pkh2(hv.x, hv.y);
        pa[(t0 + 1) * 4] = pkh2(hv.z, hv.w);
    }

    for (int side = 0; side < 2; side++) {
        const float* W    = side ? Wr : Wl;
        const float* bias = side ? br : bl;
        float* out        = side ? g_xr : g_xl;

        float acc[4][4][4];
#pragma unroll
        for (int mi = 0; mi < 4; mi++)
#pragma unroll
            for (int ni = 0; ni < 4; ni++)
#pragma unroll
                for (int q = 0; q < 4; q++) acc[mi][ni][q] = 0.f;

        for (int kh = 0; kh < 2; kh++) {
            __syncthreads();  // previous Bs fully consumed
#pragma unroll
            for (int i = 0; i < 4; i++) {
                int lin = tid + 256 * i;          // 1024 total
                int r2 = lin >> 5;                // 0..31 (k-pair)
                int c4 = (lin & 31) << 2;
                const float* w0 = W + (size_t)(kh * 64 + 2 * r2) * DD + c4;
                float4 wa = *(const float4*)w0;
                float4 wb = *(const float4*)(w0 + DD);
                uint32_t* pb = &Bs[r2 * SMPB + c4];
                pb[0] = pkh2(wa.x, wb.x);
                pb[1] = pkh2(wa.y, wb.y);
                pb[2] = pkh2(wa.z, wb.z);
                pb[3] = pkh2(wa.w, wb.w);
            }
            __syncthreads();

#pragma unroll
            for (int ks = 0; ks < 4; ks++) {      // 4 k16-steps per half
                int kb = kh * 4 + ks;
                uint4 a[4];
#pragma unroll
                for (int mi = 0; mi < 4; mi++) {
                    int Rg = wr * 4 + mi;
                    a[mi] = *(const uint4*)&As[(Rg * 8 + kb) * SMPA + lane * 4];
                }
#pragma unroll
                for (int ni = 0; ni < 4; ni++) {
                    int nb = c0 + ni * 8 + g;
                    uint32_t b0 = Bs[(ks * 8 + t) * SMPB + nb];
                    uint32_t b1 = Bs[(ks * 8 + t + 4) * SMPB + nb];
#pragma unroll
                    for (int mi = 0; mi < 4; mi++) {
                        asm volatile(
                            "mma.sync.aligned.m16n8k16.row.col.f32.f16.f16.f32 "
                            "{%0,%1,%2,%3},{%4,%5,%6,%7},{%8,%9},{%0,%1,%2,%3};"
                            : "+f"(acc[mi][ni][0]), "+f"(acc[mi][ni][1]),
                              "+f"(acc[mi][ni][2]), "+f"(acc[mi][ni][3])
                            : "r"(a[mi].x), "r"(a[mi].y), "r"(a[mi].z), "r"(a[mi].w),
                              "r"(b0), "r"(b1));
                    }
                }
            }
        }

#pragma unroll
        for (int mi = 0; mi < 4; mi++) {
#pragma unroll
            for (int ni = 0; ni < 4; ni++) {
                int cc = c0 + ni * 8 + 2 * t;
                float b0v = bias[cc], b1v = bias[cc + 1];
                int rr = rowBase + r0 + mi * 16 + g;
                *(float2*)(out + (size_t)rr * DD + cc) =
                    make_float2(acc[mi][ni][0] + b0v, acc[mi][ni][1] + b1v);
                *(float2*)(out + (size_t)(rr + 8) * DD + cc) =
                    make_float2(acc[mi][ni][2] + b0v, acc[mi][ni][3] + b1v);
            }
        }
    }
}

// ---------------- fused edge kernel: scalar fp32, 2-way chains, 3 CTAs/SM ---
// alpha = e^a / sum e^a (no max-shift: logits O(1), overflow-impossible).
template <int H>
__device__ __forceinline__ float edge_w(float4 x4, float4 xr4, float4 at4,
                                        float4 we4, float eav) {
    float m0 = x4.x + xr4.x + eav * we4.x;
    float m1 = x4.y + xr4.y + eav * we4.y;
    float m2 = x4.z + xr4.z + eav * we4.z;
    float m3 = x4.w + xr4.w + eav * we4.w;
    m0 = (m0 >= 0.f) ? m0 : 0.2f * m0;
    m1 = (m1 >= 0.f) ? m1 : 0.2f * m1;
    m2 = (m2 >= 0.f) ? m2 : 0.2f * m2;
    m3 = (m3 >= 0.f) ? m3 : 0.2f * m3;
    float p = m0 * at4.x + m1 * at4.y + m2 * at4.z + m3 * at4.w;
    p += __shfl_xor_sync(0xffffffffu, p, 1);
    p += __shfl_xor_sync(0xffffffffu, p, 2);
    p += __shfl_xor_sync(0xffffffffu, p, 4);
    if (H == 1) {
        p += __shfl_xor_sync(0xffffffffu, p, 8);
        p += __shfl_xor_sync(0xffffffffu, p, 16);
    }
    return __expf(p);
}

template <int H, bool LAST>
__global__ __launch_bounds__(256, 3)
void k_edge(const float* __restrict__ hin,
            const float* __restrict__ att, const float* __restrict__ Wev,
            const float* __restrict__ bp, const float* __restrict__ lng,
            const float* __restrict__ lnb, float* __restrict__ dout) {
    int n = blockIdx.x * 8 + (threadIdx.x >> 5);
    int l = threadIdx.x & 31;
    int col = l * 4;

    float4 xr4 = *(const float4*)(g_xr + (size_t)n * DD + col);
    float4 at4 = *(const float4*)(att + col);
    float4 we4 = *(const float4*)(Wev + col);
    int e0 = g_off[n], e1 = g_off[n + 1];

    // self-loop first (src=n, ea=mean)
    float4 xs = *(const float4*)(g_xl + (size_t)n * DD + col);
    float ws = edge_w<H>(xs, xr4, at4, we4, g_eamean);
    float ss = ws;
    float a0 = ws * xs.x, a1 = ws * xs.y, a2 = ws * xs.z, a3 = ws * xs.w;
    float ss2 = 0.f, b0 = 0.f, b1 = 0.f, b2 = 0.f, b3 = 0.f;

    int e = e0;
    for (; e + 2 <= e1; e += 2) {  // two independent chains
        int2 q0 = g_se[e];
        int2 q1 = g_se[e + 1];
        float4 xa = *(const float4*)(g_xl + (size_t)q0.x * DD + col);
        float4 xb = *(const float4*)(g_xl + (size_t)q1.x * DD + col);
        float wa = edge_w<H>(xa, xr4, at4, we4, __int_as_float(q0.y));
        float wb = edge_w<H>(xb, xr4, at4, we4, __int_as_float(q1.y));
        ss += wa;  a0 += wa * xa.x; a1 += wa * xa.y; a2 += wa * xa.z; a3 += wa * xa.w;
        ss2 += wb; b0 += wb * xb.x; b1 += wb * xb.y; b2 += wb * xb.z; b3 += wb * xb.w;
    }
    if (e < e1) {
        int2 q0 = g_se[e];
        float4 xa = *(const float4*)(g_xl + (size_t)q0.x * DD + col);
        float wa = edge_w<H>(xa, xr4, at4, we4, __int_as_float(q0.y));
        ss += wa; a0 += wa * xa.x; a1 += wa * xa.y; a2 += wa * xa.z; a3 += wa * xa.w;
    }
    ss += ss2; a0 += b0; a1 += b1; a2 += b2; a3 += b3;

    float4 bp4 = *(const float4*)(bp + col);
    float inv = 1.f / (ss + 1e-16f);
    float o0 = a0 * inv + bp4.x;
    float o1 = a1 * inv + bp4.y;
    float o2 = a2 * inv + bp4.z;
    float o3 = a3 * inv + bp4.w;

    // LayerNorm over 128 (warp-wide reduce)
    float s1 = o0 + o1 + o2 + o3;
    s1 += __shfl_xor_sync(0xffffffffu, s1, 1);
    s1 += __shfl_xor_sync(0xffffffffu, s1, 2);
    s1 += __shfl_xor_sync(0xffffffffu, s1, 4);
    s1 += __shfl_xor_sync(0xffffffffu, s1, 8);
    s1 += __shfl_xor_sync(0xffffffffu, s1, 16);
    float mu = s1 * (1.f / 128.f);
    float d0 = o0 - mu, d1 = o1 - mu, d2 = o2 - mu, d3 = o3 - mu;
    float q = d0 * d0 + d1 * d1 + d2 * d2 + d3 * d3;
    q += __shfl_xor_sync(0xffffffffu, q, 1);
    q += __shfl_xor_sync(0xffffffffu, q, 2);
    q += __shfl_xor_sync(0xffffffffu, q, 4);
    q += __shfl_xor_sync(0xffffffffu, q, 8);
    q += __shfl_xor_sync(0xffffffffu, q, 16);
    float rs = rsqrtf(q * (1.f / 128.f) + 1e-5f);
    float4 g4 = *(const float4*)(lng + col);
    float4 b4 = *(const float4*)(lnb + col);
    float y0 = d0 * rs * g4.x + b4.x;
    float y1 = d1 * rs * g4.y + b4.y;
    float y2 = d2 * rs * g4.z + b4.z;
    float y3 = d3 * rs * g4.w + b4.w;

    if (!LAST) {  // exact GELU
        const float k = 0.70710678118654752f;
        y0 = 0.5f * y0 * (1.f + erff(y0 * k));
        y1 = 0.5f * y1 * (1.f + erff(y1 * k));
        y2 = 0.5f * y2 * (1.f + erff(y2 * k));
        y3 = 0.5f * y3 * (1.f + erff(y3 * k));
    }

    float4 h4 = *(const float4*)(hin + (size_t)n * DD + col);
    h4.x += y0; h4.y += y1; h4.z += y2; h4.w += y3;

    if (!LAST) {
        *(float4*)(g_h + (size_t)n * DD + col) = h4;
    } else {  // to_dense_batch(128, 512, 128)[:, :-1, :]
        int gi = n >> 9, ii = n & 511;
        if (ii != 511)
            *(float4*)(dout + ((size_t)(gi * 511 + ii)) * DD + col) = h4;
    }
}

// ---------------- launch ----------------
extern "C" void kernel_launch(void* const* d_in, const int* in_sizes, int n_in,
                              void* d_out, int out_size) {
    const float* x     = (const float*)d_in[0];
    const int*   esrc  = (const int*)d_in[1];
    const int*   edst  = (const int*)d_in[2];
    const float* eattr = (const float*)d_in[3];
    const float* Wl    = (const float*)d_in[4];
    const float* bl    = (const float*)d_in[5];
    const float* Wr    = (const float*)d_in[6];
    const float* br    = (const float*)d_in[7];
    const float* We    = (const float*)d_in[8];
    const float* att   = (const float*)d_in[9];
    const float* bp    = (const float*)d_in[10];
    const float* lng   = (const float*)d_in[11];
    const float* lnb   = (const float*)d_in[12];
    float* out = (float*)d_out;

    void* p_h = 0; cudaGetSymbolAddress(&p_h, g_h);

    const int GSM = 64 * SMPA * 4 + 32 * SMPB * 4;  // 51200 B -> 2 CTAs/SM
    cudaFuncSetAttribute(k_gemm, cudaFuncAttributeMaxDynamicSharedMemorySize, GSM);

    k_prep<<<1024, 256>>>(edst, eattr);
    k_blocksum<<<256, 256>>>();
    k_apply<<<256, 256>>>();
    // layer-0 GEMM + fused scatter (scatter blocks fill the GEMM tail)
    k_gemm<<<512 + NE / 256, 256, GSM>>>(x, Wl, bl, Wr, br, esrc, edst, eattr);

    const float* hsrc = (const float*)p_h;
    // 5th launch: layer-0 edge (profiler capture slot)
    k_edge<4, false><<<NN / 8, 256>>>(x, att, We, bp, lng, lnb, out);
    for (int i = 1; i < 3; i++) {
        k_gemm<<<512, 256, GSM>>>(
            hsrc, Wl + i * 16384, bl + i * 128, Wr + i * 16384, br + i * 128,
            esrc, edst, eattr);
        if (i < 2)
            k_edge<4, false><<<NN / 8, 256>>>(hsrc, att + i * 128, We + i * 128, bp + i * 128,
                                              lng + i * 128, lnb + i * 128, out);
        else
            k_edge<1, true><<<NN / 8, 256>>>(hsrc, att + i * 128, We + i * 128, bp + i * 128,
                                             lng + i * 128, lnb + i * 128, out);
    }
}